// round 10
// baseline (speedup 1.0000x reference)
#include <cuda_runtime.h>
#include <cstdint>

// Problem shape (fixed by the dataset): N=8, T=256, U=128, C=512.
#define N_DIM  8
#define T_DIM  256
#define U_DIM  128
#define U1_DIM 129
#define C_DIM  512
#define ROWS   (N_DIM * T_DIM * U1_DIM)   // 264192
#define LSE_BLOCKS ((ROWS + 7) / 8)       // 33024 (8 warps per block)

// Diagonal-major scratch, PROBABILITY domain (exp of log-probs):
//   em value of cell (t,u) at [d=t+u][slot u]
//   bl value of cell (t,u) at [d=t+u][slot u+3]   (shift -> aligned 16B reads)
// PITCH=136 floats (544B = 34 x 16B cp.async segments). Pads/unwritten slots
// stay 0.0 (zero-init of __device__ globals) == exp(-inf): dead paths add 0.
#define PITCH   136
#define SEGS    34
#define DIAGS   (T_DIM + U_DIM)           // 384
#define DIAG_SZ (DIAGS * PITCH)           // 52224 per sample

#define CH      4                         // diagonals per pipeline chunk
#define NCHUNK  96                        // 384 diagonals (d = 1..384)
#define SLOTS   32                        // smem ring rows = 8 chunks in flight
#define AHEAD   7                         // chunks issued ahead of consumption

static __device__ __align__(16) float g_bld[N_DIM * DIAG_SZ + 512];  // blank (exp)
static __device__ __align__(16) float g_emd[N_DIM * DIAG_SZ + 512];  // emit  (exp)
static __device__ float    g_loss[N_DIM];
static __device__ unsigned g_cnt[N_DIM * DIAGS];  // per-(sample,diag) cell count
static __device__ unsigned g_ticket;              // last alpha block resets state

__device__ __forceinline__ void cp16(unsigned int sdst, const void* gsrc) {
    asm volatile("cp.async.cg.shared.global [%0], [%1], 16;\n"
                 :: "r"(sdst), "l"(gsrc));
}
__device__ __forceinline__ void cp_commit() {
    asm volatile("cp.async.commit_group;\n" ::: "memory");
}
__device__ __forceinline__ void cp_wait7() {
    asm volatile("cp.async.wait_group 7;\n" ::: "memory");
}
__device__ __forceinline__ void red_release(unsigned* p) {
    asm volatile("red.release.gpu.global.add.u32 [%0], 1;\n" :: "l"(p) : "memory");
}
__device__ __forceinline__ unsigned ld_acquire(const unsigned* p) {
    unsigned v;
    asm volatile("ld.acquire.gpu.global.u32 %0, [%1];\n" : "=r"(v) : "l"(p) : "memory");
    return v;
}

// number of real cells on diagonal d: t in [max(0,d-U), min(d,T-1)]
__device__ __forceinline__ unsigned diag_cells(int d) {
    int hi = min(d, T_DIM - 1);
    int lo = max(0, d - U_DIM);
    return (unsigned)(hi - lo + 1);
}

// ---------------------------------------------------------------------------
// LSE role (blocks 8..): per-row logsumexp over C=512; write exp(blank-lse),
// exp(emit-lse) into diagonal-major scratch, then RELEASE-increment the
// (sample, diagonal) counter so the alpha role can consume. HBM-bound.
// ---------------------------------------------------------------------------
__device__ __forceinline__ void lse_role(const float* __restrict__ act,
                                         const int*   __restrict__ tgt,
                                         int bid) {
    int gw   = (bid * 256 + (int)threadIdx.x) >> 5;     // global warp = row id
    int lane = threadIdx.x & 31;
    if (gw >= ROWS) return;

    const float4* p4 = reinterpret_cast<const float4*>(act) + (size_t)gw * (C_DIM / 4);
    float4 a = p4[lane];
    float4 b = p4[lane + 32];
    float4 c = p4[lane + 64];
    float4 d = p4[lane + 96];

    float m = fmaxf(fmaxf(fmaxf(a.x, a.y), fmaxf(a.z, a.w)),
                    fmaxf(fmaxf(b.x, b.y), fmaxf(b.z, b.w)));
    m = fmaxf(m, fmaxf(fmaxf(fmaxf(c.x, c.y), fmaxf(c.z, c.w)),
                       fmaxf(fmaxf(d.x, d.y), fmaxf(d.z, d.w))));
#pragma unroll
    for (int o = 16; o; o >>= 1)
        m = fmaxf(m, __shfl_xor_sync(0xffffffffu, m, o));

    float s = __expf(a.x - m) + __expf(a.y - m) + __expf(a.z - m) + __expf(a.w - m);
    s += __expf(b.x - m) + __expf(b.y - m) + __expf(b.z - m) + __expf(b.w - m);
    s += __expf(c.x - m) + __expf(c.y - m) + __expf(c.z - m) + __expf(c.w - m);
    s += __expf(d.x - m) + __expf(d.y - m) + __expf(d.z - m) + __expf(d.w - m);
#pragma unroll
    for (int o = 16; o; o >>= 1)
        s += __shfl_xor_sync(0xffffffffu, s, o);

    if (lane == 0) {
        float lse = m + __logf(s);
        int n   = gw / (T_DIM * U1_DIM);
        int rem = gw % (T_DIM * U1_DIM);
        int t   = rem / U1_DIM;
        int u   = rem % U1_DIM;
        size_t rb = (size_t)n * DIAG_SZ + (size_t)(t + u) * PITCH;
        g_bld[rb + u + 3] = __expf(a.x - lse);   // lane 0's a.x == act[row, BLANK=0]
        if (u < U_DIM) {
            int tv = __ldg(tgt + n * U_DIM + u);
            g_emd[rb + u] = __expf(__ldg(act + (size_t)gw * C_DIM + tv) - lse);
        }
        red_release(&g_cnt[n * DIAGS + t + u]);  // publish this cell
    }
}

// ---------------------------------------------------------------------------
// ALPHA role (blocks 0..7): wavefront in the PROBABILITY domain, one warp.
//   alpha(t,u) = alpha(t-1,u)*bexp(t-1,u) + alpha(t,u-1)*eexp(t,u-1)
// Lane L owns u = 4L+1..4L+4; u=0 is the pure-multiply chain a0. 2 FMA-pipe
// ops per cell, zero MUFU. Exact power-of-two renorm every 4 diagonals
// (REDUX.MAX on bit patterns; scale=2^-e; E+=e). Operands stream via a
// 32-row cp.async ring; each row is gated on its readiness counter
// (acquire-spin ~28 diagonals ahead of use -> steady-state spins are free,
// and the data is L2-hot right behind the producer). Last block (ticket)
// folds the mean and resets counters for graph replay.
// ---------------------------------------------------------------------------
__device__ __forceinline__ void alpha_role(const int* __restrict__ tlen,
                                           const int* __restrict__ ulen,
                                           float* __restrict__ out) {
    __shared__ __align__(16) float s_bl[SLOTS][PITCH];
    __shared__ __align__(16) float s_em[SLOTS][PITCH];

    int n = blockIdx.x;
    int L = threadIdx.x;                       // 0..31 (threads >=32 returned)
    const float* bld = g_bld + (size_t)n * DIAG_SZ;
    const float* emd = g_emd + (size_t)n * DIAG_SZ;
    const unsigned* cnt = g_cnt + n * DIAGS;

    int Tn = __ldg(tlen + n);
    int Un = __ldg(ulen + n);
    int dLoss = Tn - 1 + Un;

    unsigned int sbl = (unsigned int)__cvta_generic_to_shared(&s_bl[0][0]);
    unsigned int sem = (unsigned int)__cvta_generic_to_shared(&s_em[0][0]);

    // Spin until diagonal rows [r0, r1) are fully produced (lane 0, acquire).
    auto wait_rows = [&](int r0, int r1) {
        if (L == 0) {
            for (int r = r0; r < r1; ++r) {
                unsigned need = diag_cells(r);
                while (ld_acquire(cnt + r) < need) __nanosleep(64);
            }
        }
        __syncwarp();
    };

    // Copy global row -> ring slot (row & 31) for both arrays.
    auto issue_row = [&](int row) {
        unsigned int so = (unsigned int)(row & (SLOTS - 1)) * (PITCH * 4);
        const float* gb = bld + (size_t)row * PITCH;
        const float* ge = emd + (size_t)row * PITCH;
        cp16(sbl + so + 16u * L, gb + 4 * L);
        cp16(sem + so + 16u * L, ge + 4 * L);
        if (L < SEGS - 32) {                       // segments 32, 33
            cp16(sbl + so + 16u * (32 + L), gb + 4 * (32 + L));
            cp16(sem + so + 16u * (32 + L), ge + 4 * (32 + L));
        }
    };

    // Prologue: chunks 0..AHEAD-1 (rows 0..27), gated, one group per chunk.
#pragma unroll
    for (int c = 0; c < AHEAD; ++c) {
        wait_rows(4 * c, 4 * c + CH);
#pragma unroll
        for (int k = 0; k < CH; ++k) issue_row(4 * c + k);
        cp_commit();
    }

    float a0 = 1.0f;                          // alpha[0][0] = exp(0)
    float a[4] = {0.0f, 0.0f, 0.0f, 0.0f};    // 0 == prob of invalid cell
    int   E = 0;                              // accumulated power-of-two scale

    if (dLoss == 0 && L == 0)                 // degenerate Tn=1, Un=0 (row 0 ready)
        g_loss[n] = -__logf(__ldg(bld + 3));

    int d = 1;
    for (int c = 0; c < NCHUNK; ++c) {
        int rf = 4 * (c + AHEAD);             // first row of chunk c+AHEAD
        if (rf < DIAGS) {
            wait_rows(rf, rf + CH);
#pragma unroll
            for (int k = 0; k < CH; ++k) issue_row(rf + k);
        }
        cp_commit();                          // commit (possibly empty) group
        cp_wait7();                           // chunk c resident (8 in flight)
        __syncwarp();

#pragma unroll
        for (int k = 0; k < CH; ++k, ++d) {
            int s = (d - 1) & (SLOTS - 1);
            float4 blv = *reinterpret_cast<const float4*>(&s_bl[s][4 * L + 4]);
            float4 emv = *reinterpret_cast<const float4*>(&s_em[s][4 * L]);
            float  b00 = s_bl[s][3];           // col 0 blank, uniform LDS

            float nb = __shfl_up_sync(0xffffffffu, a[3], 1);  // aprev[4L]
            nb = (L == 0) ? a0 : nb;

            float t0 = fmaf(nb,   emv.x, a[0] * blv.x);
            float t1 = fmaf(a[0], emv.y, a[1] * blv.y);
            float t2 = fmaf(a[1], emv.z, a[2] * blv.z);
            float t3 = fmaf(a[2], emv.w, a[3] * blv.w);
            a0 *= b00;                         // u=0 blank-only chain
            a[0] = t0; a[1] = t1; a[2] = t2; a[3] = t3;

            if (d == dLoss) {                  // warp-uniform, true exactly once
                float fin = __ldg(bld + (size_t)dLoss * PITCH + Un + 3);
                float lv;
                if (Un == 0) {
                    lv = a0;
                } else {
                    int tl = (Un - 1) >> 2, jj = (Un - 1) & 3;
                    float v = (jj == 0) ? t0 : (jj == 1) ? t1
                            : (jj == 2) ? t2 : t3;
                    lv = __shfl_sync(0xffffffffu, v, tl);
                }
                if (L == 0)
                    g_loss[n] = -(__logf(lv) + (float)E * 0.69314718055994531f
                                  + __logf(fin));
            }
        }

        // Renormalize by exact power of two (every 4 diagonals).
        float m = fmaxf(fmaxf(a[0], a[1]), fmaxf(a[2], a[3]));
        m = fmaxf(m, a0);
        unsigned mb = __reduce_max_sync(0xffffffffu, __float_as_uint(m));
        int e = (int)(mb >> 23) - 127;                        // biased exponent
        float sc = __int_as_float((unsigned)(127 - e) << 23); // 2^-e, exact
        a[0] *= sc; a[1] *= sc; a[2] *= sc; a[3] *= sc; a0 *= sc;
        E += e;
    }

    // Last alpha block: fold mean, reset counters + ticket for graph replay.
    __syncwarp();
    __threadfence();
    unsigned tk = 0;
    if (L == 0) tk = atomicAdd(&g_ticket, 1u);
    tk = __shfl_sync(0xffffffffu, tk, 0);
    if (tk == N_DIM - 1) {
        __threadfence();
        if (L == 0) {
            float s = 0.0f;
#pragma unroll
            for (int i = 0; i < N_DIM; ++i) s += g_loss[i];
            out[0] = s / (float)N_DIM;
        }
        for (int i = L; i < N_DIM * DIAGS; i += 32) g_cnt[i] = 0;
        __syncwarp();
        if (L == 0) g_ticket = 0;
    }
}

// ---------------------------------------------------------------------------
// Fused kernel: blocks 0..7 run the alpha consumer (warp 0 only);
// blocks 8.. run the lse producer. Producers never wait -> deadlock-free.
// ---------------------------------------------------------------------------
__global__ void __launch_bounds__(256) fused_kernel(const float* __restrict__ act,
                                                    const int*   __restrict__ tgt,
                                                    const int*   __restrict__ tlen,
                                                    const int*   __restrict__ ulen,
                                                    float* __restrict__ out) {
    if (blockIdx.x < N_DIM) {
        if (threadIdx.x < 32) alpha_role(tlen, ulen, out);
        return;
    }
    lse_role(act, tgt, (int)blockIdx.x - N_DIM);
}

extern "C" void kernel_launch(void* const* d_in, const int* in_sizes, int n_in,
                              void* d_out, int out_size) {
    const float* act  = (const float*)d_in[0];
    const int*   tgt  = (const int*)  d_in[1];
    const int*   tlen = (const int*)  d_in[2];
    const int*   ulen = (const int*)  d_in[3];
    float*       out  = (float*)      d_out;

    fused_kernel<<<LSE_BLOCKS + N_DIM, 256>>>(act, tgt, tlen, ulen, out);
}

// round 11
// speedup vs baseline: 1.1358x; 1.1358x over previous
#include <cuda_runtime.h>
#include <cstdint>

// Problem shape (fixed by the dataset): N=8, T=256, U=128, C=512.
#define N_DIM  8
#define T_DIM  256
#define U_DIM  128
#define U1_DIM 129
#define C_DIM  512
#define ROWS   (N_DIM * T_DIM * U1_DIM)   // 264192

// Diagonal-major scratch, PROBABILITY domain (exp of log-probs):
//   em value of cell (t,u) at [d=t+u][slot u]
//   bl value of cell (t,u) at [d=t+u][slot u+3]   (shift -> aligned 16B reads)
// PITCH=136 floats (544B = 34 x 16B cp.async segments). Pads/unwritten slots
// stay 0.0 (zero-init of __device__ globals) == exp(-inf): dead paths add 0.
#define PITCH   136
#define SEGS    34
#define DIAGS   (T_DIM + U_DIM)           // 384
#define DIAG_SZ (DIAGS * PITCH)           // 52224 per sample

#define CH      4                         // diagonals per pipeline chunk
#define NCHUNK  96                        // 384 diagonals (d = 1..384)
#define SLOTS   32                        // smem ring rows = 8 chunks
#define AHEAD   7                         // producer wait_group depth

static __device__ __align__(16) float g_bld[N_DIM * DIAG_SZ + 512];  // blank (exp)
static __device__ __align__(16) float g_emd[N_DIM * DIAG_SZ + 512];  // emit  (exp)
static __device__ float    g_loss[N_DIM];
static __device__ unsigned g_ticket;       // zero-init; last CTA resets to 0

__device__ __forceinline__ void cp16(unsigned int sdst, const void* gsrc) {
    asm volatile("cp.async.cg.shared.global [%0], [%1], 16;\n"
                 :: "r"(sdst), "l"(gsrc));
}
__device__ __forceinline__ void cp_commit() {
    asm volatile("cp.async.commit_group;\n" ::: "memory");
}
__device__ __forceinline__ void cp_wait7() {
    asm volatile("cp.async.wait_group 7;\n" ::: "memory");
}
__device__ __forceinline__ void cp_wait0() {
    asm volatile("cp.async.wait_group 0;\n" ::: "memory");
}

// ---------------------------------------------------------------------------
// Kernel 1: per-row logsumexp over C=512; write exp(blank-lse), exp(emit-lse)
// into diagonal-major scratch. One warp per row, 4x float4 per lane.
// HBM-bound (541 MB stream, measured at the DRAM ceiling ~84%).
// ---------------------------------------------------------------------------
__global__ void __launch_bounds__(256) lse_kernel(const float* __restrict__ act,
                                                  const int*   __restrict__ tgt) {
    int gw   = (blockIdx.x * 256 + threadIdx.x) >> 5;   // global warp = row id
    int lane = threadIdx.x & 31;
    if (gw >= ROWS) return;

    const float4* p4 = reinterpret_cast<const float4*>(act) + (size_t)gw * (C_DIM / 4);
    float4 a = p4[lane];
    float4 b = p4[lane + 32];
    float4 c = p4[lane + 64];
    float4 d = p4[lane + 96];

    float m = fmaxf(fmaxf(fmaxf(a.x, a.y), fmaxf(a.z, a.w)),
                    fmaxf(fmaxf(b.x, b.y), fmaxf(b.z, b.w)));
    m = fmaxf(m, fmaxf(fmaxf(fmaxf(c.x, c.y), fmaxf(c.z, c.w)),
                       fmaxf(fmaxf(d.x, d.y), fmaxf(d.z, d.w))));
#pragma unroll
    for (int o = 16; o; o >>= 1)
        m = fmaxf(m, __shfl_xor_sync(0xffffffffu, m, o));

    float s = __expf(a.x - m) + __expf(a.y - m) + __expf(a.z - m) + __expf(a.w - m);
    s += __expf(b.x - m) + __expf(b.y - m) + __expf(b.z - m) + __expf(b.w - m);
    s += __expf(c.x - m) + __expf(c.y - m) + __expf(c.z - m) + __expf(c.w - m);
    s += __expf(d.x - m) + __expf(d.y - m) + __expf(d.z - m) + __expf(d.w - m);
#pragma unroll
    for (int o = 16; o; o >>= 1)
        s += __shfl_xor_sync(0xffffffffu, s, o);

    if (lane == 0) {
        float lse = m + __logf(s);
        int n   = gw / (T_DIM * U1_DIM);
        int rem = gw % (T_DIM * U1_DIM);
        int t   = rem / U1_DIM;
        int u   = rem % U1_DIM;
        size_t rb = (size_t)n * DIAG_SZ + (size_t)(t + u) * PITCH;
        g_bld[rb + u + 3] = __expf(a.x - lse);   // lane 0's a.x == act[row, BLANK=0]
        if (u < U_DIM) {
            int tv = __ldg(tgt + n * U_DIM + u);
            g_emd[rb + u] = __expf(__ldg(act + (size_t)gw * C_DIM + tv) - lse);
        }
    }
}

// ---------------------------------------------------------------------------
// Kernel 2: alpha wavefront, one CTA (2 warps) per sample, WARP-SPECIALIZED.
//   warp 1 (producer): streams scratch rows global->smem via a 32-row
//     cp.async ring; per chunk: 16 LDGSTS + commit; wait_group 7 then
//     threadfence_block + volatile flag s_ready. Backpressure via s_done.
//   warp 0 (consumer): pure compute in the PROBABILITY domain:
//     alpha(t,u) = alpha(t-1,u)*bexp(t-1,u) + alpha(t,u-1)*eexp(t,u-1)
//   Lane L owns u = 4L+1..4L+4; u=0 is the multiply-only chain a0.
//   2 FMA-pipe ops/cell, zero MUFU. Exact power-of-two renorm every 4
//   diagonals (REDUX.MAX on bit patterns; scale=2^-e; E+=e).
//   Final: loss = -(logf(v) + E*ln2 + logf(fin)).
// Folds the final mean via ticket atomic (last CTA, fixed-order sum).
// ---------------------------------------------------------------------------
__global__ void __launch_bounds__(64, 1) alpha_kernel(const int* __restrict__ tlen,
                                                      const int* __restrict__ ulen,
                                                      float* __restrict__ out) {
    __shared__ __align__(16) float s_bl[SLOTS][PITCH];
    __shared__ __align__(16) float s_em[SLOTS][PITCH];
    __shared__ volatile int s_ready;   // chunks fully resident in smem
    __shared__ volatile int s_done;    // chunks fully consumed

    int n    = blockIdx.x;
    int warp = threadIdx.x >> 5;
    int L    = threadIdx.x & 31;
    const float* bld = g_bld + (size_t)n * DIAG_SZ;
    const float* emd = g_emd + (size_t)n * DIAG_SZ;

    if (threadIdx.x == 0) { s_ready = 0; s_done = 0; }
    __syncthreads();

    if (warp == 1) {
        // ================= PRODUCER =================
        unsigned int sbl = (unsigned int)__cvta_generic_to_shared(&s_bl[0][0]);
        unsigned int sem = (unsigned int)__cvta_generic_to_shared(&s_em[0][0]);

        for (int c = 0; c < NCHUNK; ++c) {
            if (c >= SLOTS / CH) {                 // ring backpressure (8 chunks)
                if (L == 0) while (s_done < c - 7) { }
                __syncwarp();
            }
#pragma unroll
            for (int k = 0; k < CH; ++k) {
                int row = 4 * c + k;
                unsigned int so = (unsigned int)(row & (SLOTS - 1)) * (PITCH * 4);
                const float* gb = bld + (size_t)row * PITCH;
                const float* ge = emd + (size_t)row * PITCH;
                cp16(sbl + so + 16u * L, gb + 4 * L);
                cp16(sem + so + 16u * L, ge + 4 * L);
                if (L < SEGS - 32) {               // segments 32, 33
                    cp16(sbl + so + 16u * (32 + L), gb + 4 * (32 + L));
                    cp16(sem + so + 16u * (32 + L), ge + 4 * (32 + L));
                }
            }
            cp_commit();
            if (c >= AHEAD) {
                cp_wait7();                        // chunks 0..c-7 resident
                __threadfence_block();
                if (L == 0) s_ready = c - 6;       // count = (c-7)+1
            }
        }
        cp_wait0();
        __threadfence_block();
        if (L == 0) s_ready = NCHUNK;
        return;
    }

    // ================= CONSUMER (warp 0) =================
    int Tn = __ldg(tlen + n);
    int Un = __ldg(ulen + n);
    int dLoss = Tn - 1 + Un;

    float a0 = 1.0f;                          // alpha[0][0] = exp(0)
    float a[4] = {0.0f, 0.0f, 0.0f, 0.0f};    // 0 == prob of invalid cell
    int   E = 0;                              // accumulated power-of-two scale

    if (dLoss == 0 && L == 0)                 // degenerate Tn=1, Un=0
        g_loss[n] = -__logf(__ldg(bld + 3));

    int d = 1;
    for (int c = 0; c < NCHUNK; ++c) {
        if (L == 0) while (s_ready < c + 1) { }   // steady state: pre-satisfied
        __syncwarp();

#pragma unroll
        for (int k = 0; k < CH; ++k, ++d) {
            int s = (d - 1) & (SLOTS - 1);
            float4 blv = *reinterpret_cast<const float4*>(&s_bl[s][4 * L + 4]);
            float4 emv = *reinterpret_cast<const float4*>(&s_em[s][4 * L]);
            float  b00 = s_bl[s][3];           // col 0 blank, uniform LDS

            float nb = __shfl_up_sync(0xffffffffu, a[3], 1);  // aprev[4L]
            nb = (L == 0) ? a0 : nb;

            float t0 = fmaf(nb,   emv.x, a[0] * blv.x);
            float t1 = fmaf(a[0], emv.y, a[1] * blv.y);
            float t2 = fmaf(a[1], emv.z, a[2] * blv.z);
            float t3 = fmaf(a[2], emv.w, a[3] * blv.w);
            a0 *= b00;                         // u=0 blank-only chain
            a[0] = t0; a[1] = t1; a[2] = t2; a[3] = t3;

            if (d == dLoss) {                  // warp-uniform, true exactly once
                float fin = __ldg(bld + (size_t)dLoss * PITCH + Un + 3);
                float lv;
                if (Un == 0) {
                    lv = a0;
                } else {
                    int tl = (Un - 1) >> 2, jj = (Un - 1) & 3;
                    float v = (jj == 0) ? t0 : (jj == 1) ? t1
                            : (jj == 2) ? t2 : t3;
                    lv = __shfl_sync(0xffffffffu, v, tl);
                }
                if (L == 0)
                    g_loss[n] = -(__logf(lv) + (float)E * 0.69314718055994531f
                                  + __logf(fin));
            }
        }

        // Renormalize by exact power of two (every 4 diagonals).
        float m = fmaxf(fmaxf(a[0], a[1]), fmaxf(a[2], a[3]));
        m = fmaxf(m, a0);
        unsigned mb = __reduce_max_sync(0xffffffffu, __float_as_uint(m));
        int e = (int)(mb >> 23) - 127;                        // biased exponent
        float sc = __int_as_float((unsigned)(127 - e) << 23); // 2^-e, exact
        a[0] *= sc; a[1] *= sc; a[2] *= sc; a[3] *= sc; a0 *= sc;
        E += e;

        if (L == 0) s_done = c + 1;            // release ring slots
    }

    // Fold the mean: last CTA to arrive sums all losses in fixed order.
    __syncwarp();
    __threadfence();
    if (L == 0) {
        unsigned t = atomicAdd(&g_ticket, 1u);
        if (t == N_DIM - 1) {
            __threadfence();
            float s = 0.0f;
#pragma unroll
            for (int i = 0; i < N_DIM; ++i) s += g_loss[i];
            out[0] = s / (float)N_DIM;
            g_ticket = 0;                      // reset for next graph replay
        }
    }
}

extern "C" void kernel_launch(void* const* d_in, const int* in_sizes, int n_in,
                              void* d_out, int out_size) {
    const float* act  = (const float*)d_in[0];
    const int*   tgt  = (const int*)  d_in[1];
    const int*   tlen = (const int*)  d_in[2];
    const int*   ulen = (const int*)  d_in[3];
    float*       out  = (float*)      d_out;

    int blocks = (ROWS + 7) / 8;              // one warp per row, 8 warps/block
    lse_kernel<<<blocks, 256>>>(act, tgt);
    alpha_kernel<<<N_DIM, 64>>>(tlen, ulen, out);
}

// round 12
// speedup vs baseline: 2.2323x; 1.9654x over previous
#include <cuda_runtime.h>
#include <cstdint>

// Problem shape (fixed by the dataset): N=8, T=256, U=128, C=512.
#define N_DIM  8
#define T_DIM  256
#define U_DIM  128
#define U1_DIM 129
#define C_DIM  512
#define ROWS   (N_DIM * T_DIM * U1_DIM)   // 264192

// Diagonal-major scratch, PROBABILITY domain (exp of log-probs), PITCH=128:
//   em of cell (t,u), u<128:  g_emd[d][u]          (cols 0..127, exact fit)
//   bl of cell (t,u), u>=1:   g_bld[d][u-1]        (cols 1..128 -> slots 0..127)
//   bl of cell (t,0):         g_b0 [n][d]          (one scalar per diagonal)
// Rows are 512B; one cp.async warp-instr per row per array. Pads/unwritten
// slots stay 0.0 (zero-init) == exp(-inf): dead paths contribute 0.
#define PITCH   128
#define DIAGS   (T_DIM + U_DIM)           // 384
#define DIAG_SZ (DIAGS * PITCH)           // 49152 per sample

#define CH      8                         // diagonals per pipeline chunk
#define NCHUNK  48                        // 384 diagonals (d = 1..384)
#define SLOTS   32                        // smem ring rows = 4 chunks in flight
#define AHEAD   3                         // chunks issued ahead of consumption

static __device__ __align__(16) float g_bld[N_DIM * DIAG_SZ + 512];  // blank (exp)
static __device__ __align__(16) float g_emd[N_DIM * DIAG_SZ + 512];  // emit  (exp)
static __device__ __align__(16) float g_b0 [N_DIM * DIAGS + 128];    // blank col 0
static __device__ float    g_loss[N_DIM];
static __device__ unsigned g_ticket;       // zero-init; last CTA resets to 0

__device__ __forceinline__ void cp16(unsigned int sdst, const void* gsrc) {
    asm volatile("cp.async.cg.shared.global [%0], [%1], 16;\n"
                 :: "r"(sdst), "l"(gsrc));
}
__device__ __forceinline__ void cp_commit() {
    asm volatile("cp.async.commit_group;\n" ::: "memory");
}
__device__ __forceinline__ void cp_wait3() {
    asm volatile("cp.async.wait_group 3;\n" ::: "memory");
}

// ---------------------------------------------------------------------------
// Kernel 1: per-row logsumexp over C=512; write exp(blank-lse), exp(emit-lse)
// into the packed diagonal-major scratch. One warp per row, 4x float4/lane.
// HBM-bound (541 MB stream, measured at the DRAM ceiling ~84%).
// ---------------------------------------------------------------------------
__global__ void __launch_bounds__(256) lse_kernel(const float* __restrict__ act,
                                                  const int*   __restrict__ tgt) {
    int gw   = (blockIdx.x * 256 + threadIdx.x) >> 5;   // global warp = row id
    int lane = threadIdx.x & 31;
    if (gw >= ROWS) return;

    const float4* p4 = reinterpret_cast<const float4*>(act) + (size_t)gw * (C_DIM / 4);
    float4 a = p4[lane];
    float4 b = p4[lane + 32];
    float4 c = p4[lane + 64];
    float4 d = p4[lane + 96];

    float m = fmaxf(fmaxf(fmaxf(a.x, a.y), fmaxf(a.z, a.w)),
                    fmaxf(fmaxf(b.x, b.y), fmaxf(b.z, b.w)));
    m = fmaxf(m, fmaxf(fmaxf(fmaxf(c.x, c.y), fmaxf(c.z, c.w)),
                       fmaxf(fmaxf(d.x, d.y), fmaxf(d.z, d.w))));
#pragma unroll
    for (int o = 16; o; o >>= 1)
        m = fmaxf(m, __shfl_xor_sync(0xffffffffu, m, o));

    float s = __expf(a.x - m) + __expf(a.y - m) + __expf(a.z - m) + __expf(a.w - m);
    s += __expf(b.x - m) + __expf(b.y - m) + __expf(b.z - m) + __expf(b.w - m);
    s += __expf(c.x - m) + __expf(c.y - m) + __expf(c.z - m) + __expf(c.w - m);
    s += __expf(d.x - m) + __expf(d.y - m) + __expf(d.z - m) + __expf(d.w - m);
#pragma unroll
    for (int o = 16; o; o >>= 1)
        s += __shfl_xor_sync(0xffffffffu, s, o);

    if (lane == 0) {
        float lse = m + __logf(s);
        int n   = gw / (T_DIM * U1_DIM);
        int rem = gw % (T_DIM * U1_DIM);
        int t   = rem / U1_DIM;
        int u   = rem % U1_DIM;
        int dg  = t + u;
        float bexp = __expf(a.x - lse);       // lane 0's a.x == act[row, BLANK=0]
        size_t rb = (size_t)n * DIAG_SZ + (size_t)dg * PITCH;
        if (u == 0) g_b0[n * DIAGS + dg] = bexp;
        else        g_bld[rb + u - 1]    = bexp;
        if (u < U_DIM) {
            int tv = __ldg(tgt + n * U_DIM + u);
            g_emd[rb + u] = __expf(__ldg(act + (size_t)gw * C_DIM + tv) - lse);
        }
    }
}

// ---------------------------------------------------------------------------
// Kernel 2: alpha wavefront, ONE WARP per sample, PROBABILITY domain.
//   alpha(t,u) = alpha(t-1,u)*bexp(t-1,u) + alpha(t,u-1)*eexp(t,u-1)
// Lane L owns u = 4L+1..4L+4 (a[0..3]); u=0 is the multiply-only chain a0
// (factor from the smem-resident b0 table, loaded once at prologue).
// 2 FMA-pipe ops per cell, zero MUFU. Exact power-of-two renorm every 8
// diagonals (REDUX.MAX on bit patterns; scale = 2^-e; E += e).
// Final: loss = -(logf(v) + E*ln2 + logf(fin)).
// Operands stream via a 32-row cp.async ring, 2 warp-instrs per row
// (packed layout), 4 chunks = 32 diagonals in flight; one wait_group +
// syncwarp per 8 diagonals. Folds the final mean via ticket atomic.
// ---------------------------------------------------------------------------
__global__ void __launch_bounds__(32, 1) alpha_kernel(const int* __restrict__ tlen,
                                                      const int* __restrict__ ulen,
                                                      float* __restrict__ out) {
    __shared__ __align__(16) float s_bl[SLOTS][PITCH];
    __shared__ __align__(16) float s_em[SLOTS][PITCH];
    __shared__ __align__(16) float s_b0[DIAGS];

    int n = blockIdx.x;
    int L = threadIdx.x;
    const float* bld = g_bld + (size_t)n * DIAG_SZ;
    const float* emd = g_emd + (size_t)n * DIAG_SZ;
    const float* b0g = g_b0  + n * DIAGS;

    int Tn = __ldg(tlen + n);
    int Un = __ldg(ulen + n);
    int dLoss = Tn - 1 + Un;

    unsigned int sbl = (unsigned int)__cvta_generic_to_shared(&s_bl[0][0]);
    unsigned int sem = (unsigned int)__cvta_generic_to_shared(&s_em[0][0]);
    unsigned int sb0 = (unsigned int)__cvta_generic_to_shared(&s_b0[0]);

    // Copy global row -> ring slot (row & 31): one 16B segment per lane.
    auto issue_row = [&](int row) {
        unsigned int so = (unsigned int)(row & (SLOTS - 1)) * (PITCH * 4);
        cp16(sbl + so + 16u * L, bld + (size_t)row * PITCH + 4 * L);
        cp16(sem + so + 16u * L, emd + (size_t)row * PITCH + 4 * L);
    };

    // Prologue: whole b0 table (384 floats = 3 warp-instrs) + chunks 0..2.
    cp16(sb0 + 16u * L,         b0g + 4 * L);
    cp16(sb0 + 16u * (L + 32),  b0g + 4 * (L + 32));
    cp16(sb0 + 16u * (L + 64),  b0g + 4 * (L + 64));
#pragma unroll
    for (int c = 0; c < AHEAD; ++c) {
#pragma unroll
        for (int k = 0; k < CH; ++k) issue_row(CH * c + k);
        cp_commit();
    }

    float a0 = 1.0f;                          // alpha[0][0] = exp(0)
    float a[4] = {0.0f, 0.0f, 0.0f, 0.0f};    // 0 == prob of invalid cell
    int   E = 0;                              // accumulated power-of-two scale

    if (dLoss == 0 && L == 0)                 // degenerate Tn=1, Un=0
        g_loss[n] = -__logf(__ldg(b0g));

    int d = 1;
    for (int c = 0; c < NCHUNK; ++c) {
        int rf = CH * (c + AHEAD);            // first row of chunk c+AHEAD
        if (rf < DIAGS) {
#pragma unroll
            for (int k = 0; k < CH; ++k) issue_row(rf + k);
        }
        cp_commit();                          // commit (possibly empty) group
        cp_wait3();                           // chunk c resident (4 in flight)
        __syncwarp();

#pragma unroll
        for (int k = 0; k < CH; ++k, ++d) {
            int s = (d - 1) & (SLOTS - 1);
            float4 blv = *reinterpret_cast<const float4*>(&s_bl[s][4 * L]);
            float4 emv = *reinterpret_cast<const float4*>(&s_em[s][4 * L]);
            float  b00 = s_b0[d - 1];          // uniform LDS broadcast

            float nb = __shfl_up_sync(0xffffffffu, a[3], 1);  // aprev[4L]
            nb = (L == 0) ? a0 : nb;

            float t0 = fmaf(nb,   emv.x, a[0] * blv.x);
            float t1 = fmaf(a[0], emv.y, a[1] * blv.y);
            float t2 = fmaf(a[1], emv.z, a[2] * blv.z);
            float t3 = fmaf(a[2], emv.w, a[3] * blv.w);
            a0 *= b00;                         // u=0 blank-only chain
            a[0] = t0; a[1] = t1; a[2] = t2; a[3] = t3;

            if (d == dLoss) {                  // warp-uniform, true exactly once
                float fin = (Un == 0) ? __ldg(b0g + dLoss)
                          : __ldg(bld + (size_t)dLoss * PITCH + Un - 1);
                float lv;
                if (Un == 0) {
                    lv = a0;
                } else {
                    int tl = (Un - 1) >> 2, jj = (Un - 1) & 3;
                    float v = (jj == 0) ? t0 : (jj == 1) ? t1
                            : (jj == 2) ? t2 : t3;
                    lv = __shfl_sync(0xffffffffu, v, tl);
                }
                if (L == 0)
                    g_loss[n] = -(__logf(lv) + (float)E * 0.69314718055994531f
                                  + __logf(fin));
            }
        }

        // Renormalize by exact power of two (every 8 diagonals).
        float m = fmaxf(fmaxf(a[0], a[1]), fmaxf(a[2], a[3]));
        m = fmaxf(m, a0);
        unsigned mb = __reduce_max_sync(0xffffffffu, __float_as_uint(m));
        int e = (int)(mb >> 23) - 127;                        // biased exponent
        float sc = __int_as_float((unsigned)(127 - e) << 23); // 2^-e, exact
        a[0] *= sc; a[1] *= sc; a[2] *= sc; a[3] *= sc; a0 *= sc;
        E += e;
    }

    // Fold the mean: last CTA to arrive sums all losses in fixed order.
    __syncwarp();
    __threadfence();
    if (L == 0) {
        unsigned t = atomicAdd(&g_ticket, 1u);
        if (t == N_DIM - 1) {
            __threadfence();
            float s = 0.0f;
#pragma unroll
            for (int i = 0; i < N_DIM; ++i) s += g_loss[i];
            out[0] = s / (float)N_DIM;
            g_ticket = 0;                      // reset for next graph replay
        }
    }
}

extern "C" void kernel_launch(void* const* d_in, const int* in_sizes, int n_in,
                              void* d_out, int out_size) {
    const float* act  = (const float*)d_in[0];
    const int*   tgt  = (const int*)  d_in[1];
    const int*   tlen = (const int*)  d_in[2];
    const int*   ulen = (const int*)  d_in[3];
    float*       out  = (float*)      d_out;

    int blocks = (ROWS + 7) / 8;              // one warp per row, 8 warps/block
    lse_kernel<<<blocks, 256>>>(act, tgt);
    alpha_kernel<<<N_DIM, 32>>>(tlen, ulen, out);
}